// round 7
// baseline (speedup 1.0000x reference)
#include <cuda_runtime.h>

#define HW 1024

// Scratch buffers
__device__ float g_qkv[8 * 192 * HW];        // [b][192][1024]; q pre-scaled by dkh^-0.5*log2e
__device__ float g_convp[4 * 8 * 64 * HW];   // [cs][b][64][1024] conv partial sums (no bias)
__device__ float g_pacc[4 * 8 * 64 * HW];    // [wq][b][64][1024] partial softmax-weighted V sums
__device__ float g_pssum[4 * 8 * 8 * HW];    // [wq][b][n][1024] partial exp sums

typedef unsigned long long u64;

__device__ __forceinline__ u64 fma2(u64 a, u64 b, u64 c) {
  u64 d; asm("fma.rn.f32x2 %0,%1,%2,%3;" : "=l"(d) : "l"(a), "l"(b), "l"(c)); return d;
}
__device__ __forceinline__ u64 add2(u64 a, u64 b) {
  u64 d; asm("add.rn.f32x2 %0,%1,%2;" : "=l"(d) : "l"(a), "l"(b)); return d;
}
__device__ __forceinline__ u64 pack2(float lo, float hi) {
  u64 d; asm("mov.b64 %0,{%1,%2};" : "=l"(d) : "f"(lo), "f"(hi)); return d;
}
__device__ __forceinline__ void unpack2(u64 v, float& lo, float& hi) {
  asm("mov.b64 {%0,%1},%2;" : "=f"(lo), "=f"(hi) : "l"(v));
}
__device__ __forceinline__ float ex2f(float x) {
  float y; asm("ex2.approx.ftz.f32 %0,%1;" : "=f"(y) : "f"(x)); return y;
}

// ---------------------------------------------------------------------------
// Fused prep.
// blocks [0,512): conv3x3 c-split partials. blk -> cs(4) x b(8) x og(16),
//   16 input channels each, FMA2 over vertical pixel pairs, planar staging.
// blocks [512,896): qkv 1x1 projection into g_qkv.
// 256 threads, 48KB dynamic smem, 3 blocks/SM.
// ---------------------------------------------------------------------------
__global__ __launch_bounds__(256, 3) void prep_kernel(
    const float* __restrict__ x,
    const float* __restrict__ conv_w,
    const float* __restrict__ qkv_w, const float* __restrict__ qkv_b,
    float* __restrict__ convp, float* __restrict__ qkv_out) {
  extern __shared__ char smraw[];
  int blk = blockIdx.x;
  int t = threadIdx.x;

  if (blk < 512) {
    // ---------------- conv 3x3 partial: 16 channels ----------------
    u64* wdup = (u64*)smraw;                 // [4 o][16 c][9] dup u64
    float* xs = (float*)(smraw + 4608);      // [8 cc][34][34] planar
    int cs = blk >> 7;
    int rem = blk & 127;
    int b = rem >> 4, og = rem & 15;
    int cbase = cs * 16;

    for (int i = t; i < 576; i += 256) {
      int o = i / 144, r2 = i - o * 144;
      float wv = conv_w[(og * 4 + o) * 576 + cbase * 9 + r2];
      wdup[i] = pack2(wv, wv);
    }
    for (int i = t; i < 9248; i += 256) xs[i] = 0.f;

    int xcol = t & 31, m0 = t >> 5;
    u64 acc[4][2];
#pragma unroll
    for (int o = 0; o < 4; o++) { acc[o][0] = 0ull; acc[o][1] = 0ull; }

    for (int chunk = 0; chunk < 2; chunk++) {
      __syncthreads();
#pragma unroll
      for (int cc = 0; cc < 8; cc++) {
        const float* xp = x + (b * 64 + cbase + chunk * 8 + cc) * HW;
#pragma unroll
        for (int rg = 0; rg < 4; rg++) {
          int row = rg * 8 + m0;
          xs[cc * 1156 + (row + 1) * 34 + xcol + 1] = xp[row * 32 + xcol];
        }
      }
      __syncthreads();

#pragma unroll
      for (int cc = 0; cc < 8; cc++) {
        const float* xc = xs + cc * 1156;
        int crel = chunk * 8 + cc;
        u64 pr[2][9];
#pragma unroll
        for (int pi = 0; pi < 2; pi++) {
          int m = m0 + pi * 8;
          const float* base = xc + (2 * m) * 34 + xcol;
#pragma unroll
          for (int kw = 0; kw < 3; kw++) {
            float s0 = base[kw], s1 = base[34 + kw];
            float s2 = base[68 + kw], s3 = base[102 + kw];
            pr[pi][0 + kw] = pack2(s0, s1);
            pr[pi][3 + kw] = pack2(s1, s2);
            pr[pi][6 + kw] = pack2(s2, s3);
          }
        }
        const u64* wc = wdup + crel * 9;
#pragma unroll
        for (int o = 0; o < 4; o++) {
          const u64* wo = wc + o * 144;
          u64 a0 = acc[o][0], a1 = acc[o][1];
#pragma unroll
          for (int k = 0; k < 9; k++) {
            u64 wk = wo[k];
            a0 = fma2(pr[0][k], wk, a0);
            a1 = fma2(pr[1][k], wk, a1);
          }
          acc[o][0] = a0; acc[o][1] = a1;
        }
      }
    }

    float* cpb = convp + (cs * 8 + b) * 64 * HW + og * 4 * HW;
#pragma unroll
    for (int o = 0; o < 4; o++) {
#pragma unroll
      for (int pi = 0; pi < 2; pi++) {
        int m = m0 + pi * 8;
        float lo, hi; unpack2(acc[o][pi], lo, hi);
        cpb[o * HW + (2 * m) * 32 + xcol] = lo;
        cpb[o * HW + (2 * m + 1) * 32 + xcol] = hi;
      }
    }
  } else {
    // ---------------- qkv 1x1 projection ----------------
    float* xs = (float*)smraw;               // [64][128] 32KB
    u64* ws2 = (u64*)(smraw + 32768);        // [64][32]  16KB
    int r = blk - 512;
    int b = r / 48;
    int rem = r - b * 48;
    int og = rem >> 3, pt = rem & 7;
    int p0 = pt * 128;

    for (int i = t; i < 64 * 128; i += 256) {
      int c = i >> 7, pp = i & 127;
      xs[i] = x[(b * 64 + c) * HW + p0 + pp];
    }
    for (int i = t; i < 64 * 32; i += 256) {
      int c = i >> 5, o = i & 31;
      float wv = qkv_w[(og * 32 + o) * 64 + c];
      ws2[i] = pack2(wv, wv);
    }
    __syncthreads();

    int oi = t >> 5, pi = t & 31;
    u64 acc2[4][2];
#pragma unroll
    for (int a = 0; a < 4; a++) { acc2[a][0] = 0ull; acc2[a][1] = 0ull; }

    for (int c0 = 0; c0 < 64; c0 += 4) {
      u64 xv[4][2], wv[4][4];
#pragma unroll
      for (int cc = 0; cc < 4; cc++) {
        xv[cc][0] = *(const u64*)(xs + (c0 + cc) * 128 + pi * 2);
        xv[cc][1] = *(const u64*)(xs + (c0 + cc) * 128 + 64 + pi * 2);
      }
#pragma unroll
      for (int cc = 0; cc < 4; cc++)
#pragma unroll
        for (int a = 0; a < 4; a++) wv[cc][a] = ws2[(c0 + cc) * 32 + oi * 4 + a];
#pragma unroll
      for (int cc = 0; cc < 4; cc++)
#pragma unroll
        for (int a = 0; a < 4; a++) {
          acc2[a][0] = fma2(wv[cc][a], xv[cc][0], acc2[a][0]);
          acc2[a][1] = fma2(wv[cc][a], xv[cc][1], acc2[a][1]);
        }
    }

#pragma unroll
    for (int a = 0; a < 4; a++) {
      int o = og * 32 + oi * 4 + a;
      float bb = qkv_b[o];
      float sc = (o < 64) ? (0.35355339059327373f * 1.4426950408889634f) : 1.f;
      float* ob = qkv_out + (b * 192 + o) * HW + p0;
#pragma unroll
      for (int k = 0; k < 2; k++) {
        float lo, hi; unpack2(acc2[a][k], lo, hi);
        *(float2*)(ob + 64 * k + pi * 2) = make_float2(sc * (lo + bb), sc * (hi + bb));
      }
    }
  }
}

// ---------------------------------------------------------------------------
// Attention partials. grid (64 bn, 2 rowhalf, 4 wquarter), block 128.
// Thread owns 4 rows (2 packed pairs); block covers j's with w2 in quarter.
// smem ~54.4KB -> 4 blocks/SM; ~124 reg budget via __launch_bounds__(128,4).
// ---------------------------------------------------------------------------
#define AT_KD    0
#define AT_VD    16384
#define AT_RWT   32768                 // [8 w2l][256 pairs] u64 = 16384
#define AT_RELW  49152                 // 504 floats
#define AT_RELHD (AT_RELW + 2016)      // 504 u64
#define AT_SMEM  (AT_RELHD + 4032)     // 55200 bytes

__global__ __launch_bounds__(128, 4) void attn_kernel(
    const float* __restrict__ qkv,
    const float* __restrict__ relw, const float* __restrict__ relh,
    float* __restrict__ pacc, float* __restrict__ pssum) {
  extern __shared__ char sm[];
  int t = threadIdx.x;
  int bn = blockIdx.x;
  int b = bn >> 3, n = bn & 7;
  int rowhalf = blockIdx.y;
  int wq = blockIdx.z;

  const float* qb = qkv + (b * 192 + n * 8) * HW;
  const float* kb = qkv + (b * 192 + 64 + n * 8) * HW;
  const float* vb = qkv + (b * 192 + 128 + n * 8) * HW;

  // stage this w-quarter of K,V duplicated: jl = h2*8 + w2l
  u64* kdup = (u64*)(sm + AT_KD);
  u64* vdup = (u64*)(sm + AT_VD);
  for (int e = t; e < 2048; e += 128) {
    int jl = e >> 3, d = e & 7;
    int h2 = jl >> 3, w2l = jl & 7;
    int j = h2 * 32 + wq * 8 + w2l;
    float kv = kb[d * HW + j];
    float vv = vb[d * HW + j];
    kdup[jl * 8 + d] = pack2(kv, kv);
    vdup[jl * 8 + d] = pack2(vv, vv);
  }
  float* s_relw = (float*)(sm + AT_RELW);
  for (int e = t; e < 504; e += 128) {
    s_relw[e] = relw[e];
    float rv = relh[e];
    *(u64*)(sm + AT_RELHD + e * 8) = pack2(rv, rv);
  }
  __syncthreads();

  // rows i0..i0+3; pairs (i0,i0+1) and (i0+2,i0+3); all share h1
  int i0 = rowhalf * 512 + 4 * t;
  int h1 = i0 >> 5, w1 = i0 & 31;   // w1 multiple of 4, <= 28

  u64 q2a[8], q2b[8];
  float ql0[8], ql1[8], ql2[8], ql3[8];
#pragma unroll
  for (int d = 0; d < 8; d++) {
    float4 qv = *(const float4*)(qb + d * HW + i0);
    ql0[d] = qv.x; ql1[d] = qv.y; ql2[d] = qv.z; ql3[d] = qv.w;
    q2a[d] = pack2(qv.x, qv.y);
    q2b[d] = pack2(qv.z, qv.w);
  }

  // rw table: [w2l][256 pairs]; this thread fills pairs 2t, 2t+1
  u64* rwt = (u64*)(sm + AT_RWT);
#pragma unroll
  for (int w2l = 0; w2l < 8; w2l++) {
    int w2 = wq * 8 + w2l;
    const float* r0 = s_relw + (w2 - w1 + 31) * 8;   // row i0
    float a0 = 0.f, a1 = 0.f, a2 = 0.f, a3 = 0.f;
#pragma unroll
    for (int d = 0; d < 8; d++) {
      a0 += ql0[d] * r0[d];
      a1 += ql1[d] * r0[d - 8];
      a2 += ql2[d] * r0[d - 16];
      a3 += ql3[d] * r0[d - 24];
    }
    rwt[w2l * 256 + 2 * t] = pack2(a0, a1);
    rwt[w2l * 256 + 2 * t + 1] = pack2(a2, a3);
  }

  u64 acca[8], accb[8], ssuma = 0ull, ssumb = 0ull;
#pragma unroll
  for (int d = 0; d < 8; d++) { acca[d] = 0ull; accb[d] = 0ull; }

  for (int h2 = 0; h2 < 32; h2++) {
    const u64* rhp = (const u64*)(sm + AT_RELHD) + (h2 - h1 + 31) * 8;
    u64 rha = 0ull, rhb = 0ull;
#pragma unroll
    for (int d = 0; d < 8; d++) {
      u64 rv = rhp[d];
      rha = fma2(q2a[d], rv, rha);
      rhb = fma2(q2b[d], rv, rhb);
    }

#pragma unroll
    for (int w2l = 0; w2l < 8; w2l++) {
      int jl = h2 * 8 + w2l;
      const ulonglong2* kj = (const ulonglong2*)(kdup + jl * 8);
      ulonglong2 k0 = kj[0], k1 = kj[1], k2 = kj[2], k3 = kj[3];
      ulonglong2 rw = *(const ulonglong2*)(rwt + w2l * 256 + 2 * t);
      u64 sa = add2(rw.x, rha);
      u64 sb = add2(rw.y, rhb);
      sa = fma2(q2a[0], k0.x, sa); sb = fma2(q2b[0], k0.x, sb);
      sa = fma2(q2a[1], k0.y, sa); sb = fma2(q2b[1], k0.y, sb);
      sa = fma2(q2a[2], k1.x, sa); sb = fma2(q2b[2], k1.x, sb);
      sa = fma2(q2a[3], k1.y, sa); sb = fma2(q2b[3], k1.y, sb);
      sa = fma2(q2a[4], k2.x, sa); sb = fma2(q2b[4], k2.x, sb);
      sa = fma2(q2a[5], k2.y, sa); sb = fma2(q2b[5], k2.y, sb);
      sa = fma2(q2a[6], k3.x, sa); sb = fma2(q2b[6], k3.x, sb);
      sa = fma2(q2a[7], k3.y, sa); sb = fma2(q2b[7], k3.y, sb);
      float s0, s1, s2, s3;
      unpack2(sa, s0, s1); unpack2(sb, s2, s3);
      u64 pa = pack2(ex2f(s0), ex2f(s1));
      u64 pb = pack2(ex2f(s2), ex2f(s3));
      ssuma = add2(ssuma, pa);
      ssumb = add2(ssumb, pb);
      const ulonglong2* vj = (const ulonglong2*)(vdup + jl * 8);
      ulonglong2 v0 = vj[0], v1 = vj[1], v2 = vj[2], v3 = vj[3];
      acca[0] = fma2(pa, v0.x, acca[0]); accb[0] = fma2(pb, v0.x, accb[0]);
      acca[1] = fma2(pa, v0.y, acca[1]); accb[1] = fma2(pb, v0.y, accb[1]);
      acca[2] = fma2(pa, v1.x, acca[2]); accb[2] = fma2(pb, v1.x, accb[2]);
      acca[3] = fma2(pa, v1.y, acca[3]); accb[3] = fma2(pb, v1.y, accb[3]);
      acca[4] = fma2(pa, v2.x, acca[4]); accb[4] = fma2(pb, v2.x, accb[4]);
      acca[5] = fma2(pa, v2.y, acca[5]); accb[5] = fma2(pb, v2.y, accb[5]);
      acca[6] = fma2(pa, v3.x, acca[6]); accb[6] = fma2(pb, v3.x, accb[6]);
      acca[7] = fma2(pa, v3.y, acca[7]); accb[7] = fma2(pb, v3.y, accb[7]);
    }
  }

  float sa0, sa1, sb0, sb1;
  unpack2(ssuma, sa0, sa1); unpack2(ssumb, sb0, sb1);
  *(float4*)(pssum + ((wq * 8 + b) * 8 + n) * HW + i0) =
      make_float4(sa0, sa1, sb0, sb1);
  float* ab = pacc + ((wq * 8 + b) * 64 + n * 8) * HW + i0;
#pragma unroll
  for (int d = 0; d < 8; d++) {
    float a0, a1, b0, b1;
    unpack2(acca[d], a0, a1); unpack2(accb[d], b0, b1);
    *(float4*)(ab + d * HW) = make_float4(a0, a1, b0, b1);
  }
}

// ---------------------------------------------------------------------------
// Output projection: merges 4 attn partials + softmax division + GEMM
// (out ch 64..127). og==0 blocks also merge the 4 conv partials (ch 0..63).
// grid (8 b, 2 og, 8 pt), block 256.
// ---------------------------------------------------------------------------
__global__ __launch_bounds__(256) void proj_kernel(
    const float* __restrict__ pacc, const float* __restrict__ pssum,
    const float* __restrict__ convp, const float* __restrict__ conv_b,
    const float* __restrict__ w, const float* __restrict__ bias,
    float* __restrict__ out) {
  extern __shared__ char smraw[];
  float* invs = (float*)smraw;                     // [8][128] 4KB
  float* xs = (float*)(smraw + 4096);              // [64][128] 32KB
  u64* ws2 = (u64*)(smraw + 4096 + 32768);         // [64][32] 16KB
  int b = blockIdx.x, og = blockIdx.y, pt = blockIdx.z;
  int t = threadIdx.x;
  int p0 = pt * 128;

  for (int i = t; i < 1024; i += 256) {
    int n = i >> 7, pp = i & 127;
    int idx = (b * 8 + n) * HW + p0 + pp;
    float s = pssum[idx] + pssum[idx + 64 * HW] +
              pssum[idx + 128 * HW] + pssum[idx + 192 * HW];
    invs[i] = 1.f / s;
  }
  for (int i = t; i < 64 * 32; i += 256) {
    int c = i >> 5, o = i & 31;
    float wv = w[(og * 32 + o) * 64 + c];
    ws2[i] = pack2(wv, wv);
  }
  __syncthreads();
  for (int i = t; i < 64 * 128; i += 256) {
    int c = i >> 7, pp = i & 127;
    int idx = (b * 64 + c) * HW + p0 + pp;
    float s = pacc[idx] + pacc[idx + 512 * HW] +
              pacc[idx + 1024 * HW] + pacc[idx + 1536 * HW];
    xs[i] = s * invs[(c >> 3) * 128 + pp];
  }
  __syncthreads();

  int oi = t >> 5, pi = t & 31;
  u64 acc2[4][2];
#pragma unroll
  for (int a = 0; a < 4; a++) { acc2[a][0] = 0ull; acc2[a][1] = 0ull; }

  for (int c0 = 0; c0 < 64; c0 += 4) {
    u64 xv[4][2], wv[4][4];
#pragma unroll
    for (int cc = 0; cc < 4; cc++) {
      xv[cc][0] = *(const u64*)(xs + (c0 + cc) * 128 + pi * 2);
      xv[cc][1] = *(const u64*)(xs + (c0 + cc) * 128 + 64 + pi * 2);
    }
#pragma unroll
    for (int cc = 0; cc < 4; cc++)
#pragma unroll
      for (int a = 0; a < 4; a++) wv[cc][a] = ws2[(c0 + cc) * 32 + oi * 4 + a];
#pragma unroll
    for (int cc = 0; cc < 4; cc++)
#pragma unroll
      for (int a = 0; a < 4; a++) {
        acc2[a][0] = fma2(wv[cc][a], xv[cc][0], acc2[a][0]);
        acc2[a][1] = fma2(wv[cc][a], xv[cc][1], acc2[a][1]);
      }
  }

#pragma unroll
  for (int a = 0; a < 4; a++) {
    int o = og * 32 + oi * 4 + a;
    float bb = bias[o];
    float* ob = out + (b * 128 + 64 + o) * HW + p0;
#pragma unroll
    for (int k = 0; k < 2; k++) {
      float lo, hi; unpack2(acc2[a][k], lo, hi);
      *(float2*)(ob + 64 * k + pi * 2) = make_float2(lo + bb, hi + bb);
    }
  }

  if (og == 0) {
    for (int i = t; i < 64 * 128; i += 256) {
      int oc = i >> 7, pp = i & 127;
      int idx = (b * 64 + oc) * HW + p0 + pp;
      float s = convp[idx] + convp[idx + 512 * HW] +
                convp[idx + 1024 * HW] + convp[idx + 1536 * HW];
      out[(b * 128 + oc) * HW + p0 + pp] = s + conv_b[oc];
    }
  }
}

// ---------------------------------------------------------------------------
extern "C" void kernel_launch(void* const* d_in, const int* in_sizes, int n_in,
                              void* d_out, int out_size) {
  (void)in_sizes; (void)n_in; (void)out_size;
  const float* x      = (const float*)d_in[0];
  const float* conv_w = (const float*)d_in[1];
  const float* conv_b = (const float*)d_in[2];
  const float* qkv_w  = (const float*)d_in[3];
  const float* qkv_b  = (const float*)d_in[4];
  const float* attn_w = (const float*)d_in[5];
  const float* attn_b = (const float*)d_in[6];
  const float* relw   = (const float*)d_in[7];
  const float* relh   = (const float*)d_in[8];
  float* out = (float*)d_out;

  float *qkv_s = nullptr, *convp = nullptr, *pacc = nullptr, *pssum = nullptr;
  cudaGetSymbolAddress((void**)&qkv_s, g_qkv);
  cudaGetSymbolAddress((void**)&convp, g_convp);
  cudaGetSymbolAddress((void**)&pacc, g_pacc);
  cudaGetSymbolAddress((void**)&pssum, g_pssum);

  const int PREP_SMEM = 49152;
  const int PROJ_SMEM = 4096 + 32768 + 16384;
  cudaFuncSetAttribute(prep_kernel, cudaFuncAttributeMaxDynamicSharedMemorySize, PREP_SMEM);
  cudaFuncSetAttribute(attn_kernel, cudaFuncAttributeMaxDynamicSharedMemorySize, AT_SMEM);
  cudaFuncSetAttribute(proj_kernel, cudaFuncAttributeMaxDynamicSharedMemorySize, PROJ_SMEM);

  prep_kernel<<<896, 256, PREP_SMEM>>>(x, conv_w, qkv_w, qkv_b, convp, qkv_s);
  attn_kernel<<<dim3(64, 2, 4), 128, AT_SMEM>>>(qkv_s, relw, relh, pacc, pssum);
  proj_kernel<<<dim3(8, 2, 8), 256, PROJ_SMEM>>>(pacc, pssum, convp, conv_b,
                                                 attn_w, attn_b, out);
}

// round 8
// speedup vs baseline: 1.0301x; 1.0301x over previous
#include <cuda_runtime.h>

#define HW 1024

// Scratch buffers
__device__ float g_qkv[8 * 192 * HW];        // [b][192][1024]; q pre-scaled by dkh^-0.5*log2e
__device__ float g_convp[4 * 8 * 64 * HW];   // [cs][b][64][1024] conv partial sums (no bias)
__device__ float g_pacc[4 * 8 * 64 * HW];    // [wq][b][64][1024] partial softmax-weighted V sums
__device__ float g_pssum[4 * 8 * 8 * HW];    // [wq][b][n][1024] partial exp sums

typedef unsigned long long u64;

__device__ __forceinline__ u64 fma2(u64 a, u64 b, u64 c) {
  u64 d; asm("fma.rn.f32x2 %0,%1,%2,%3;" : "=l"(d) : "l"(a), "l"(b), "l"(c)); return d;
}
__device__ __forceinline__ u64 add2(u64 a, u64 b) {
  u64 d; asm("add.rn.f32x2 %0,%1,%2;" : "=l"(d) : "l"(a), "l"(b)); return d;
}
__device__ __forceinline__ u64 pack2(float lo, float hi) {
  u64 d; asm("mov.b64 %0,{%1,%2};" : "=l"(d) : "f"(lo), "f"(hi)); return d;
}
__device__ __forceinline__ void unpack2(u64 v, float& lo, float& hi) {
  asm("mov.b64 {%0,%1},%2;" : "=f"(lo), "=f"(hi) : "l"(v));
}
__device__ __forceinline__ float ex2f(float x) {
  float y; asm("ex2.approx.ftz.f32 %0,%1;" : "=f"(y) : "f"(x)); return y;
}

// ---------------------------------------------------------------------------
// Fused prep (unchanged from R6).
// blocks [0,512): conv3x3 c-split partials; blocks [512,896): qkv projection.
// ---------------------------------------------------------------------------
__global__ __launch_bounds__(256, 3) void prep_kernel(
    const float* __restrict__ x,
    const float* __restrict__ conv_w,
    const float* __restrict__ qkv_w, const float* __restrict__ qkv_b,
    float* __restrict__ convp, float* __restrict__ qkv_out) {
  extern __shared__ char smraw[];
  int blk = blockIdx.x;
  int t = threadIdx.x;

  if (blk < 512) {
    u64* wdup = (u64*)smraw;                 // [4 o][16 c][9] dup u64
    float* xs = (float*)(smraw + 4608);      // [8 cc][34][34] planar
    int cs = blk >> 7;
    int rem = blk & 127;
    int b = rem >> 4, og = rem & 15;
    int cbase = cs * 16;

    for (int i = t; i < 576; i += 256) {
      int o = i / 144, r2 = i - o * 144;
      float wv = conv_w[(og * 4 + o) * 576 + cbase * 9 + r2];
      wdup[i] = pack2(wv, wv);
    }
    for (int i = t; i < 9248; i += 256) xs[i] = 0.f;

    int xcol = t & 31, m0 = t >> 5;
    u64 acc[4][2];
#pragma unroll
    for (int o = 0; o < 4; o++) { acc[o][0] = 0ull; acc[o][1] = 0ull; }

    for (int chunk = 0; chunk < 2; chunk++) {
      __syncthreads();
#pragma unroll
      for (int cc = 0; cc < 8; cc++) {
        const float* xp = x + (b * 64 + cbase + chunk * 8 + cc) * HW;
#pragma unroll
        for (int rg = 0; rg < 4; rg++) {
          int row = rg * 8 + m0;
          xs[cc * 1156 + (row + 1) * 34 + xcol + 1] = xp[row * 32 + xcol];
        }
      }
      __syncthreads();

#pragma unroll
      for (int cc = 0; cc < 8; cc++) {
        const float* xc = xs + cc * 1156;
        int crel = chunk * 8 + cc;
        u64 pr[2][9];
#pragma unroll
        for (int pi = 0; pi < 2; pi++) {
          int m = m0 + pi * 8;
          const float* base = xc + (2 * m) * 34 + xcol;
#pragma unroll
          for (int kw = 0; kw < 3; kw++) {
            float s0 = base[kw], s1 = base[34 + kw];
            float s2 = base[68 + kw], s3 = base[102 + kw];
            pr[pi][0 + kw] = pack2(s0, s1);
            pr[pi][3 + kw] = pack2(s1, s2);
            pr[pi][6 + kw] = pack2(s2, s3);
          }
        }
        const u64* wc = wdup + crel * 9;
#pragma unroll
        for (int o = 0; o < 4; o++) {
          const u64* wo = wc + o * 144;
          u64 a0 = acc[o][0], a1 = acc[o][1];
#pragma unroll
          for (int k = 0; k < 9; k++) {
            u64 wk = wo[k];
            a0 = fma2(pr[0][k], wk, a0);
            a1 = fma2(pr[1][k], wk, a1);
          }
          acc[o][0] = a0; acc[o][1] = a1;
        }
      }
    }

    float* cpb = convp + (cs * 8 + b) * 64 * HW + og * 4 * HW;
#pragma unroll
    for (int o = 0; o < 4; o++) {
#pragma unroll
      for (int pi = 0; pi < 2; pi++) {
        int m = m0 + pi * 8;
        float lo, hi; unpack2(acc[o][pi], lo, hi);
        cpb[o * HW + (2 * m) * 32 + xcol] = lo;
        cpb[o * HW + (2 * m + 1) * 32 + xcol] = hi;
      }
    }
  } else {
    float* xs = (float*)smraw;               // [64][128] 32KB
    u64* ws2 = (u64*)(smraw + 32768);        // [64][32]  16KB
    int r = blk - 512;
    int b = r / 48;
    int rem = r - b * 48;
    int og = rem >> 3, pt = rem & 7;
    int p0 = pt * 128;

    for (int i = t; i < 64 * 128; i += 256) {
      int c = i >> 7, pp = i & 127;
      xs[i] = x[(b * 64 + c) * HW + p0 + pp];
    }
    for (int i = t; i < 64 * 32; i += 256) {
      int c = i >> 5, o = i & 31;
      float wv = qkv_w[(og * 32 + o) * 64 + c];
      ws2[i] = pack2(wv, wv);
    }
    __syncthreads();

    int oi = t >> 5, pi = t & 31;
    u64 acc2[4][2];
#pragma unroll
    for (int a = 0; a < 4; a++) { acc2[a][0] = 0ull; acc2[a][1] = 0ull; }

    for (int c0 = 0; c0 < 64; c0 += 4) {
      u64 xv[4][2], wv[4][4];
#pragma unroll
      for (int cc = 0; cc < 4; cc++) {
        xv[cc][0] = *(const u64*)(xs + (c0 + cc) * 128 + pi * 2);
        xv[cc][1] = *(const u64*)(xs + (c0 + cc) * 128 + 64 + pi * 2);
      }
#pragma unroll
      for (int cc = 0; cc < 4; cc++)
#pragma unroll
        for (int a = 0; a < 4; a++) wv[cc][a] = ws2[(c0 + cc) * 32 + oi * 4 + a];
#pragma unroll
      for (int cc = 0; cc < 4; cc++)
#pragma unroll
        for (int a = 0; a < 4; a++) {
          acc2[a][0] = fma2(wv[cc][a], xv[cc][0], acc2[a][0]);
          acc2[a][1] = fma2(wv[cc][a], xv[cc][1], acc2[a][1]);
        }
    }

#pragma unroll
    for (int a = 0; a < 4; a++) {
      int o = og * 32 + oi * 4 + a;
      float bb = qkv_b[o];
      float sc = (o < 64) ? (0.35355339059327373f * 1.4426950408889634f) : 1.f;
      float* ob = qkv_out + (b * 192 + o) * HW + p0;
#pragma unroll
      for (int k = 0; k < 2; k++) {
        float lo, hi; unpack2(acc2[a][k], lo, hi);
        *(float2*)(ob + 64 * k + pi * 2) = make_float2(sc * (lo + bb), sc * (hi + bb));
      }
    }
  }
}

// ---------------------------------------------------------------------------
// Attention v4: f32x2 packs J-PAIRS (q duplicated in regs; K/V planar in smem
// so LDS.128 yields two fma2-ready j-pair operands directly).
// grid (64 bn, 4 rowg, 4 wq), block 128; thread owns rows (i0, i0+1),
// covers j's with w2 in its 8-wide quarter. smem ~33.8KB -> 4 blocks/SM.
// ---------------------------------------------------------------------------
#define AT4_K    0                     // [8 d][256 jl] f32 = 8192
#define AT4_V    8192                  // 8192
#define AT4_RWT  16384                 // [128 t][9] u64 = 9216
#define AT4_RELW 25600                 // 504 u64 dup = 4032
#define AT4_RELH 29632                 // 4032
#define AT4_SMEM 33792

__global__ __launch_bounds__(128, 4) void attn_kernel(
    const float* __restrict__ qkv,
    const float* __restrict__ relw, const float* __restrict__ relh,
    float* __restrict__ pacc, float* __restrict__ pssum) {
  extern __shared__ char sm[];
  float* kpl = (float*)(sm + AT4_K);
  float* vpl = (float*)(sm + AT4_V);
  u64* rwt = (u64*)(sm + AT4_RWT);
  u64* relwd = (u64*)(sm + AT4_RELW);
  u64* relhd = (u64*)(sm + AT4_RELH);
  int t = threadIdx.x;
  int bn = blockIdx.x;
  int b = bn >> 3, n = bn & 7;
  int rowg = blockIdx.y;   // 0..3
  int wq = blockIdx.z;     // 0..3

  const float* qb = qkv + (b * 192 + n * 8) * HW;
  const float* kb = qkv + (b * 192 + 64 + n * 8) * HW;
  const float* vb = qkv + (b * 192 + 128 + n * 8) * HW;

  // stage K,V planar: jl = h2*8 + w2l <-> j = h2*32 + wq*8 + w2l
  for (int e = t; e < 2048; e += 128) {
    int d = e >> 8, jl = e & 255;
    int j = (jl >> 3) * 32 + wq * 8 + (jl & 7);
    kpl[e] = kb[d * HW + j];
    vpl[e] = vb[d * HW + j];
  }
  for (int e = t; e < 504; e += 128) {
    float a = relw[e]; relwd[e] = pack2(a, a);
    float c = relh[e]; relhd[e] = pack2(c, c);
  }
  __syncthreads();

  int i0 = rowg * 256 + 2 * t;       // rows i0, i0+1 (same h1; w1 <= 30)
  int h1 = i0 >> 5, w1 = i0 & 31;

  u64 q2[2][8];
#pragma unroll
  for (int d = 0; d < 8; d++) {
    float2 qv = *(const float2*)(qb + d * HW + i0);
    q2[0][d] = pack2(qv.x, qv.x);
    q2[1][d] = pack2(qv.y, qv.y);
  }

  // per-thread rw table: myrwt[r*4+p] = (rw[r][w2=wq*8+2p], rw[r][w2+1])
  u64* myrwt = rwt + t * 9;
#pragma unroll
  for (int r = 0; r < 2; r++) {
#pragma unroll
    for (int p = 0; p < 4; p++) {
      int m0 = wq * 8 + 2 * p - (w1 + r) + 31;
      u64 z0 = 0ull, z1 = 0ull;
#pragma unroll
      for (int d = 0; d < 8; d++) {
        z0 = fma2(q2[r][d], relwd[m0 * 8 + d], z0);
        z1 = fma2(q2[r][d], relwd[(m0 + 1) * 8 + d], z1);
      }
      float alo, ahi, blo, bhi;
      unpack2(z0, alo, ahi); unpack2(z1, blo, bhi);
      myrwt[r * 4 + p] = pack2(alo, blo);
    }
  }

  u64 acc2[2][8];
  u64 ssum2[2] = {0ull, 0ull};
#pragma unroll
  for (int d = 0; d < 8; d++) { acc2[0][d] = 0ull; acc2[1][d] = 0ull; }

#pragma unroll 1
  for (int h2 = 0; h2 < 32; h2++) {
    const u64* rhp = relhd + (h2 - h1 + 31) * 8;
    u64 rh0 = 0ull, rh1 = 0ull;
#pragma unroll
    for (int d = 0; d < 8; d++) {
      u64 rv = rhp[d];
      rh0 = fma2(q2[0][d], rv, rh0);
      rh1 = fma2(q2[1][d], rv, rh1);
    }

#pragma unroll
    for (int cw = 0; cw < 2; cw++) {
      int base = h2 * 8 + cw * 4;     // 4 consecutive jl, 16B aligned
      u64 s2a0 = add2(myrwt[2 * cw], rh0);       // row0: (j0, j1)
      u64 s2b0 = add2(myrwt[2 * cw + 1], rh0);   // row0: (j2, j3)
      u64 s2a1 = add2(myrwt[4 + 2 * cw], rh1);
      u64 s2b1 = add2(myrwt[4 + 2 * cw + 1], rh1);
#pragma unroll
      for (int d = 0; d < 8; d++) {
        ulonglong2 kk = *(const ulonglong2*)(kpl + d * 256 + base);
        s2a0 = fma2(q2[0][d], kk.x, s2a0);
        s2b0 = fma2(q2[0][d], kk.y, s2b0);
        s2a1 = fma2(q2[1][d], kk.x, s2a1);
        s2b1 = fma2(q2[1][d], kk.y, s2b1);
      }
      float x0, x1, x2, x3;
      unpack2(s2a0, x0, x1); unpack2(s2b0, x2, x3);
      u64 pa0 = pack2(ex2f(x0), ex2f(x1));
      u64 pb0 = pack2(ex2f(x2), ex2f(x3));
      unpack2(s2a1, x0, x1); unpack2(s2b1, x2, x3);
      u64 pa1 = pack2(ex2f(x0), ex2f(x1));
      u64 pb1 = pack2(ex2f(x2), ex2f(x3));
      ssum2[0] = add2(ssum2[0], add2(pa0, pb0));
      ssum2[1] = add2(ssum2[1], add2(pa1, pb1));
#pragma unroll
      for (int d = 0; d < 8; d++) {
        ulonglong2 vv = *(const ulonglong2*)(vpl + d * 256 + base);
        acc2[0][d] = fma2(pa0, vv.x, acc2[0][d]);
        acc2[0][d] = fma2(pb0, vv.y, acc2[0][d]);
        acc2[1][d] = fma2(pa1, vv.x, acc2[1][d]);
        acc2[1][d] = fma2(pb1, vv.y, acc2[1][d]);
      }
    }
  }

  float s0lo, s0hi, s1lo, s1hi;
  unpack2(ssum2[0], s0lo, s0hi);
  unpack2(ssum2[1], s1lo, s1hi);
  *(float2*)(pssum + ((wq * 8 + b) * 8 + n) * HW + i0) =
      make_float2(s0lo + s0hi, s1lo + s1hi);
  float* ab = pacc + ((wq * 8 + b) * 64 + n * 8) * HW + i0;
#pragma unroll
  for (int d = 0; d < 8; d++) {
    float a0, a1, b0, b1;
    unpack2(acc2[0][d], a0, a1);
    unpack2(acc2[1][d], b0, b1);
    *(float2*)(ab + d * HW) = make_float2(a0 + a1, b0 + b1);
  }
}

// ---------------------------------------------------------------------------
// Output projection (unchanged): merges 4 attn partials + softmax division +
// GEMM (ch 64..127); og==0 blocks merge the 4 conv partials (ch 0..63).
// ---------------------------------------------------------------------------
__global__ __launch_bounds__(256) void proj_kernel(
    const float* __restrict__ pacc, const float* __restrict__ pssum,
    const float* __restrict__ convp, const float* __restrict__ conv_b,
    const float* __restrict__ w, const float* __restrict__ bias,
    float* __restrict__ out) {
  extern __shared__ char smraw[];
  float* invs = (float*)smraw;                     // [8][128] 4KB
  float* xs = (float*)(smraw + 4096);              // [64][128] 32KB
  u64* ws2 = (u64*)(smraw + 4096 + 32768);         // [64][32] 16KB
  int b = blockIdx.x, og = blockIdx.y, pt = blockIdx.z;
  int t = threadIdx.x;
  int p0 = pt * 128;

  for (int i = t; i < 1024; i += 256) {
    int n = i >> 7, pp = i & 127;
    int idx = (b * 8 + n) * HW + p0 + pp;
    float s = pssum[idx] + pssum[idx + 64 * HW] +
              pssum[idx + 128 * HW] + pssum[idx + 192 * HW];
    invs[i] = 1.f / s;
  }
  for (int i = t; i < 64 * 32; i += 256) {
    int c = i >> 5, o = i & 31;
    float wv = w[(og * 32 + o) * 64 + c];
    ws2[i] = pack2(wv, wv);
  }
  __syncthreads();
  for (int i = t; i < 64 * 128; i += 256) {
    int c = i >> 7, pp = i & 127;
    int idx = (b * 64 + c) * HW + p0 + pp;
    float s = pacc[idx] + pacc[idx + 512 * HW] +
              pacc[idx + 1024 * HW] + pacc[idx + 1536 * HW];
    xs[i] = s * invs[(c >> 3) * 128 + pp];
  }
  __syncthreads();

  int oi = t >> 5, pi = t & 31;
  u64 acc2[4][2];
#pragma unroll
  for (int a = 0; a < 4; a++) { acc2[a][0] = 0ull; acc2[a][1] = 0ull; }

  for (int c0 = 0; c0 < 64; c0 += 4) {
    u64 xv[4][2], wv[4][4];
#pragma unroll
    for (int cc = 0; cc < 4; cc++) {
      xv[cc][0] = *(const u64*)(xs + (c0 + cc) * 128 + pi * 2);
      xv[cc][1] = *(const u64*)(xs + (c0 + cc) * 128 + 64 + pi * 2);
    }
#pragma unroll
    for (int cc = 0; cc < 4; cc++)
#pragma unroll
      for (int a = 0; a < 4; a++) wv[cc][a] = ws2[(c0 + cc) * 32 + oi * 4 + a];
#pragma unroll
    for (int cc = 0; cc < 4; cc++)
#pragma unroll
      for (int a = 0; a < 4; a++) {
        acc2[a][0] = fma2(wv[cc][a], xv[cc][0], acc2[a][0]);
        acc2[a][1] = fma2(wv[cc][a], xv[cc][1], acc2[a][1]);
      }
  }

#pragma unroll
  for (int a = 0; a < 4; a++) {
    int o = og * 32 + oi * 4 + a;
    float bb = bias[o];
    float* ob = out + (b * 128 + 64 + o) * HW + p0;
#pragma unroll
    for (int k = 0; k < 2; k++) {
      float lo, hi; unpack2(acc2[a][k], lo, hi);
      *(float2*)(ob + 64 * k + pi * 2) = make_float2(lo + bb, hi + bb);
    }
  }

  if (og == 0) {
    for (int i = t; i < 64 * 128; i += 256) {
      int oc = i >> 7, pp = i & 127;
      int idx = (b * 64 + oc) * HW + p0 + pp;
      float s = convp[idx] + convp[idx + 512 * HW] +
                convp[idx + 1024 * HW] + convp[idx + 1536 * HW];
      out[(b * 128 + oc) * HW + p0 + pp] = s + conv_b[oc];
    }
  }
}

// ---------------------------------------------------------------------------
extern "C" void kernel_launch(void* const* d_in, const int* in_sizes, int n_in,
                              void* d_out, int out_size) {
  (void)in_sizes; (void)n_in; (void)out_size;
  const float* x      = (const float*)d_in[0];
  const float* conv_w = (const float*)d_in[1];
  const float* conv_b = (const float*)d_in[2];
  const float* qkv_w  = (const float*)d_in[3];
  const float* qkv_b  = (const float*)d_in[4];
  const float* attn_w = (const float*)d_in[5];
  const float* attn_b = (const float*)d_in[6];
  const float* relw   = (const float*)d_in[7];
  const float* relh   = (const float*)d_in[8];
  float* out = (float*)d_out;

  float *qkv_s = nullptr, *convp = nullptr, *pacc = nullptr, *pssum = nullptr;
  cudaGetSymbolAddress((void**)&qkv_s, g_qkv);
  cudaGetSymbolAddress((void**)&convp, g_convp);
  cudaGetSymbolAddress((void**)&pacc, g_pacc);
  cudaGetSymbolAddress((void**)&pssum, g_pssum);

  const int PREP_SMEM = 49152;
  const int PROJ_SMEM = 4096 + 32768 + 16384;
  cudaFuncSetAttribute(prep_kernel, cudaFuncAttributeMaxDynamicSharedMemorySize, PREP_SMEM);
  cudaFuncSetAttribute(attn_kernel, cudaFuncAttributeMaxDynamicSharedMemorySize, AT4_SMEM);
  cudaFuncSetAttribute(proj_kernel, cudaFuncAttributeMaxDynamicSharedMemorySize, PROJ_SMEM);

  prep_kernel<<<896, 256, PREP_SMEM>>>(x, conv_w, qkv_w, qkv_b, convp, qkv_s);
  attn_kernel<<<dim3(64, 4, 4), 128, AT4_SMEM>>>(qkv_s, relw, relh, pacc, pssum);
  proj_kernel<<<dim3(8, 2, 8), 256, PROJ_SMEM>>>(pacc, pssum, convp, conv_b,
                                                 attn_w, attn_b, out);
}

// round 11
// speedup vs baseline: 1.0502x; 1.0194x over previous
#include <cuda_runtime.h>

#define HW 1024

// Scratch buffers
__device__ float g_qkv[8 * 192 * HW];        // [b][192][1024]; q pre-scaled by dkh^-0.5*log2e
__device__ float g_convp[4 * 8 * 64 * HW];   // [cs][b][64][1024] conv partial sums (no bias)
__device__ float g_pacc[4 * 8 * 64 * HW];    // [wq][b][64][1024] partial softmax-weighted V sums
__device__ float g_pssum[4 * 8 * 8 * HW];    // [wq][b][n][1024] partial exp sums

typedef unsigned long long u64;

__device__ __forceinline__ u64 fma2(u64 a, u64 b, u64 c) {
  u64 d; asm("fma.rn.f32x2 %0,%1,%2,%3;" : "=l"(d) : "l"(a), "l"(b), "l"(c)); return d;
}
__device__ __forceinline__ u64 add2(u64 a, u64 b) {
  u64 d; asm("add.rn.f32x2 %0,%1,%2;" : "=l"(d) : "l"(a), "l"(b)); return d;
}
__device__ __forceinline__ u64 pack2(float lo, float hi) {
  u64 d; asm("mov.b64 %0,{%1,%2};" : "=l"(d) : "f"(lo), "f"(hi)); return d;
}
__device__ __forceinline__ void unpack2(u64 v, float& lo, float& hi) {
  asm("mov.b64 {%0,%1},%2;" : "=f"(lo), "=f"(hi) : "l"(v));
}
__device__ __forceinline__ float ex2f(float x) {
  float y; asm("ex2.approx.ftz.f32 %0,%1;" : "=f"(y) : "f"(x)); return y;
}

// ---------------------------------------------------------------------------
// Fused prep (unchanged).
// blocks [0,512): conv3x3 c-split partials; blocks [512,896): qkv projection.
// ---------------------------------------------------------------------------
__global__ __launch_bounds__(256, 3) void prep_kernel(
    const float* __restrict__ x,
    const float* __restrict__ conv_w,
    const float* __restrict__ qkv_w, const float* __restrict__ qkv_b,
    float* __restrict__ convp, float* __restrict__ qkv_out) {
  extern __shared__ char smraw[];
  int blk = blockIdx.x;
  int t = threadIdx.x;

  if (blk < 512) {
    u64* wdup = (u64*)smraw;                 // [4 o][16 c][9] dup u64
    float* xs = (float*)(smraw + 4608);      // [8 cc][34][34] planar
    int cs = blk >> 7;
    int rem = blk & 127;
    int b = rem >> 4, og = rem & 15;
    int cbase = cs * 16;

    for (int i = t; i < 576; i += 256) {
      int o = i / 144, r2 = i - o * 144;
      float wv = conv_w[(og * 4 + o) * 576 + cbase * 9 + r2];
      wdup[i] = pack2(wv, wv);
    }
    for (int i = t; i < 9248; i += 256) xs[i] = 0.f;

    int xcol = t & 31, m0 = t >> 5;
    u64 acc[4][2];
#pragma unroll
    for (int o = 0; o < 4; o++) { acc[o][0] = 0ull; acc[o][1] = 0ull; }

    for (int chunk = 0; chunk < 2; chunk++) {
      __syncthreads();
#pragma unroll
      for (int cc = 0; cc < 8; cc++) {
        const float* xp = x + (b * 64 + cbase + chunk * 8 + cc) * HW;
#pragma unroll
        for (int rg = 0; rg < 4; rg++) {
          int row = rg * 8 + m0;
          xs[cc * 1156 + (row + 1) * 34 + xcol + 1] = xp[row * 32 + xcol];
        }
      }
      __syncthreads();

#pragma unroll
      for (int cc = 0; cc < 8; cc++) {
        const float* xc = xs + cc * 1156;
        int crel = chunk * 8 + cc;
        u64 pr[2][9];
#pragma unroll
        for (int pi = 0; pi < 2; pi++) {
          int m = m0 + pi * 8;
          const float* base = xc + (2 * m) * 34 + xcol;
#pragma unroll
          for (int kw = 0; kw < 3; kw++) {
            float s0 = base[kw], s1 = base[34 + kw];
            float s2 = base[68 + kw], s3 = base[102 + kw];
            pr[pi][0 + kw] = pack2(s0, s1);
            pr[pi][3 + kw] = pack2(s1, s2);
            pr[pi][6 + kw] = pack2(s2, s3);
          }
        }
        const u64* wc = wdup + crel * 9;
#pragma unroll
        for (int o = 0; o < 4; o++) {
          const u64* wo = wc + o * 144;
          u64 a0 = acc[o][0], a1 = acc[o][1];
#pragma unroll
          for (int k = 0; k < 9; k++) {
            u64 wk = wo[k];
            a0 = fma2(pr[0][k], wk, a0);
            a1 = fma2(pr[1][k], wk, a1);
          }
          acc[o][0] = a0; acc[o][1] = a1;
        }
      }
    }

    float* cpb = convp + (cs * 8 + b) * 64 * HW + og * 4 * HW;
#pragma unroll
    for (int o = 0; o < 4; o++) {
#pragma unroll
      for (int pi = 0; pi < 2; pi++) {
        int m = m0 + pi * 8;
        float lo, hi; unpack2(acc[o][pi], lo, hi);
        cpb[o * HW + (2 * m) * 32 + xcol] = lo;
        cpb[o * HW + (2 * m + 1) * 32 + xcol] = hi;
      }
    }
  } else {
    float* xs = (float*)smraw;               // [64][128] 32KB
    u64* ws2 = (u64*)(smraw + 32768);        // [64][32]  16KB
    int r = blk - 512;
    int b = r / 48;
    int rem = r - b * 48;
    int og = rem >> 3, pt = rem & 7;
    int p0 = pt * 128;

    for (int i = t; i < 64 * 128; i += 256) {
      int c = i >> 7, pp = i & 127;
      xs[i] = x[(b * 64 + c) * HW + p0 + pp];
    }
    for (int i = t; i < 64 * 32; i += 256) {
      int c = i >> 5, o = i & 31;
      float wv = qkv_w[(og * 32 + o) * 64 + c];
      ws2[i] = pack2(wv, wv);
    }
    __syncthreads();

    int oi = t >> 5, pi = t & 31;
    u64 acc2[4][2];
#pragma unroll
    for (int a = 0; a < 4; a++) { acc2[a][0] = 0ull; acc2[a][1] = 0ull; }

    for (int c0 = 0; c0 < 64; c0 += 4) {
      u64 xv[4][2], wv[4][4];
#pragma unroll
      for (int cc = 0; cc < 4; cc++) {
        xv[cc][0] = *(const u64*)(xs + (c0 + cc) * 128 + pi * 2);
        xv[cc][1] = *(const u64*)(xs + (c0 + cc) * 128 + 64 + pi * 2);
      }
#pragma unroll
      for (int cc = 0; cc < 4; cc++)
#pragma unroll
        for (int a = 0; a < 4; a++) wv[cc][a] = ws2[(c0 + cc) * 32 + oi * 4 + a];
#pragma unroll
      for (int cc = 0; cc < 4; cc++)
#pragma unroll
        for (int a = 0; a < 4; a++) {
          acc2[a][0] = fma2(wv[cc][a], xv[cc][0], acc2[a][0]);
          acc2[a][1] = fma2(wv[cc][a], xv[cc][1], acc2[a][1]);
        }
    }

#pragma unroll
    for (int a = 0; a < 4; a++) {
      int o = og * 32 + oi * 4 + a;
      float bb = qkv_b[o];
      float sc = (o < 64) ? (0.35355339059327373f * 1.4426950408889634f) : 1.f;
      float* ob = qkv_out + (b * 192 + o) * HW + p0;
#pragma unroll
      for (int k = 0; k < 2; k++) {
        float lo, hi; unpack2(acc2[a][k], lo, hi);
        *(float2*)(ob + 64 * k + pi * 2) = make_float2(sc * (lo + bb), sc * (hi + bb));
      }
    }
  }
}

// ---------------------------------------------------------------------------
// Attention v4 (identical dataflow to R8) with __launch_bounds__(128, 3):
// 170-reg budget removes hot-loop spills; 3 blocks/SM (101KB smem).
// grid (64 bn, 4 rowg, 4 wq), block 128; thread owns rows (i0, i0+1).
// ---------------------------------------------------------------------------
#define AT4_K    0                     // [8 d][256 jl] f32 = 8192
#define AT4_V    8192                  // 8192
#define AT4_RWT  16384                 // [128 t][9] u64 = 9216
#define AT4_RELW 25600                 // 504 u64 dup = 4032
#define AT4_RELH 29632                 // 4032
#define AT4_SMEM 33792

__global__ __launch_bounds__(128, 3) void attn_kernel(
    const float* __restrict__ qkv,
    const float* __restrict__ relw, const float* __restrict__ relh,
    float* __restrict__ pacc, float* __restrict__ pssum) {
  extern __shared__ char sm[];
  float* kpl = (float*)(sm + AT4_K);
  float* vpl = (float*)(sm + AT4_V);
  u64* rwt = (u64*)(sm + AT4_RWT);
  u64* relwd = (u64*)(sm + AT4_RELW);
  u64* relhd = (u64*)(sm + AT4_RELH);
  int t = threadIdx.x;
  int bn = blockIdx.x;
  int b = bn >> 3, n = bn & 7;
  int rowg = blockIdx.y;   // 0..3
  int wq = blockIdx.z;     // 0..3

  const float* qb = qkv + (b * 192 + n * 8) * HW;
  const float* kb = qkv + (b * 192 + 64 + n * 8) * HW;
  const float* vb = qkv + (b * 192 + 128 + n * 8) * HW;

  // stage K,V planar: jl = h2*8 + w2l <-> j = h2*32 + wq*8 + w2l
  for (int e = t; e < 2048; e += 128) {
    int d = e >> 8, jl = e & 255;
    int j = (jl >> 3) * 32 + wq * 8 + (jl & 7);
    kpl[e] = kb[d * HW + j];
    vpl[e] = vb[d * HW + j];
  }
  for (int e = t; e < 504; e += 128) {
    float a = relw[e]; relwd[e] = pack2(a, a);
    float c = relh[e]; relhd[e] = pack2(c, c);
  }
  __syncthreads();

  int i0 = rowg * 256 + 2 * t;       // rows i0, i0+1 (same h1; w1 <= 30)
  int h1 = i0 >> 5, w1 = i0 & 31;

  u64 q2[2][8];
#pragma unroll
  for (int d = 0; d < 8; d++) {
    float2 qv = *(const float2*)(qb + d * HW + i0);
    q2[0][d] = pack2(qv.x, qv.x);
    q2[1][d] = pack2(qv.y, qv.y);
  }

  // per-thread rw table: myrwt[r*4+p] = (rw[r][w2=wq*8+2p], rw[r][w2+1])
  u64* myrwt = rwt + t * 9;
#pragma unroll
  for (int r = 0; r < 2; r++) {
#pragma unroll
    for (int p = 0; p < 4; p++) {
      int m0 = wq * 8 + 2 * p - (w1 + r) + 31;
      u64 z0 = 0ull, z1 = 0ull;
#pragma unroll
      for (int d = 0; d < 8; d++) {
        z0 = fma2(q2[r][d], relwd[m0 * 8 + d], z0);
        z1 = fma2(q2[r][d], relwd[(m0 + 1) * 8 + d], z1);
      }
      float alo, ahi, blo, bhi;
      unpack2(z0, alo, ahi); unpack2(z1, blo, bhi);
      myrwt[r * 4 + p] = pack2(alo, blo);
    }
  }

  u64 acc2[2][8];
  u64 ssum2[2] = {0ull, 0ull};
#pragma unroll
  for (int d = 0; d < 8; d++) { acc2[0][d] = 0ull; acc2[1][d] = 0ull; }

#pragma unroll 1
  for (int h2 = 0; h2 < 32; h2++) {
    const u64* rhp = relhd + (h2 - h1 + 31) * 8;
    u64 rh0 = 0ull, rh1 = 0ull;
#pragma unroll
    for (int d = 0; d < 8; d++) {
      u64 rv = rhp[d];
      rh0 = fma2(q2[0][d], rv, rh0);
      rh1 = fma2(q2[1][d], rv, rh1);
    }

#pragma unroll
    for (int cw = 0; cw < 2; cw++) {
      int base = h2 * 8 + cw * 4;     // 4 consecutive jl, 16B aligned
      u64 s2a0 = add2(myrwt[2 * cw], rh0);       // row0: (j0, j1)
      u64 s2b0 = add2(myrwt[2 * cw + 1], rh0);   // row0: (j2, j3)
      u64 s2a1 = add2(myrwt[4 + 2 * cw], rh1);
      u64 s2b1 = add2(myrwt[4 + 2 * cw + 1], rh1);
#pragma unroll
      for (int d = 0; d < 8; d++) {
        ulonglong2 kk = *(const ulonglong2*)(kpl + d * 256 + base);
        s2a0 = fma2(q2[0][d], kk.x, s2a0);
        s2b0 = fma2(q2[0][d], kk.y, s2b0);
        s2a1 = fma2(q2[1][d], kk.x, s2a1);
        s2b1 = fma2(q2[1][d], kk.y, s2b1);
      }
      float x0, x1, x2, x3;
      unpack2(s2a0, x0, x1); unpack2(s2b0, x2, x3);
      u64 pa0 = pack2(ex2f(x0), ex2f(x1));
      u64 pb0 = pack2(ex2f(x2), ex2f(x3));
      unpack2(s2a1, x0, x1); unpack2(s2b1, x2, x3);
      u64 pa1 = pack2(ex2f(x0), ex2f(x1));
      u64 pb1 = pack2(ex2f(x2), ex2f(x3));
      ssum2[0] = add2(ssum2[0], add2(pa0, pb0));
      ssum2[1] = add2(ssum2[1], add2(pa1, pb1));
#pragma unroll
      for (int d = 0; d < 8; d++) {
        ulonglong2 vv = *(const ulonglong2*)(vpl + d * 256 + base);
        acc2[0][d] = fma2(pa0, vv.x, acc2[0][d]);
        acc2[0][d] = fma2(pb0, vv.y, acc2[0][d]);
        acc2[1][d] = fma2(pa1, vv.x, acc2[1][d]);
        acc2[1][d] = fma2(pb1, vv.y, acc2[1][d]);
      }
    }
  }

  float s0lo, s0hi, s1lo, s1hi;
  unpack2(ssum2[0], s0lo, s0hi);
  unpack2(ssum2[1], s1lo, s1hi);
  *(float2*)(pssum + ((wq * 8 + b) * 8 + n) * HW + i0) =
      make_float2(s0lo + s0hi, s1lo + s1hi);
  float* ab = pacc + ((wq * 8 + b) * 64 + n * 8) * HW + i0;
#pragma unroll
  for (int d = 0; d < 8; d++) {
    float a0, a1, b0, b1;
    unpack2(acc2[0][d], a0, a1);
    unpack2(acc2[1][d], b0, b1);
    *(float2*)(ab + d * HW) = make_float2(a0 + a1, b0 + b1);
  }
}

// ---------------------------------------------------------------------------
// Output projection (unchanged): merges 4 attn partials + softmax division +
// GEMM (ch 64..127); og==0 blocks merge the 4 conv partials (ch 0..63).
// ---------------------------------------------------------------------------
__global__ __launch_bounds__(256) void proj_kernel(
    const float* __restrict__ pacc, const float* __restrict__ pssum,
    const float* __restrict__ convp, const float* __restrict__ conv_b,
    const float* __restrict__ w, const float* __restrict__ bias,
    float* __restrict__ out) {
  extern __shared__ char smraw[];
  float* invs = (float*)smraw;                     // [8][128] 4KB
  float* xs = (float*)(smraw + 4096);              // [64][128] 32KB
  u64* ws2 = (u64*)(smraw + 4096 + 32768);         // [64][32] 16KB
  int b = blockIdx.x, og = blockIdx.y, pt = blockIdx.z;
  int t = threadIdx.x;
  int p0 = pt * 128;

  for (int i = t; i < 1024; i += 256) {
    int n = i >> 7, pp = i & 127;
    int idx = (b * 8 + n) * HW + p0 + pp;
    float s = pssum[idx] + pssum[idx + 64 * HW] +
              pssum[idx + 128 * HW] + pssum[idx + 192 * HW];
    invs[i] = 1.f / s;
  }
  for (int i = t; i < 64 * 32; i += 256) {
    int c = i >> 5, o = i & 31;
    float wv = w[(og * 32 + o) * 64 + c];
    ws2[i] = pack2(wv, wv);
  }
  __syncthreads();
  for (int i = t; i < 64 * 128; i += 256) {
    int c = i >> 7, pp = i & 127;
    int idx = (b * 64 + c) * HW + p0 + pp;
    float s = pacc[idx] + pacc[idx + 512 * HW] +
              pacc[idx + 1024 * HW] + pacc[idx + 1536 * HW];
    xs[i] = s * invs[(c >> 3) * 128 + pp];
  }
  __syncthreads();

  int oi = t >> 5, pi = t & 31;
  u64 acc2[4][2];
#pragma unroll
  for (int a = 0; a < 4; a++) { acc2[a][0] = 0ull; acc2[a][1] = 0ull; }

  for (int c0 = 0; c0 < 64; c0 += 4) {
    u64 xv[4][2], wv[4][4];
#pragma unroll
    for (int cc = 0; cc < 4; cc++) {
      xv[cc][0] = *(const u64*)(xs + (c0 + cc) * 128 + pi * 2);
      xv[cc][1] = *(const u64*)(xs + (c0 + cc) * 128 + 64 + pi * 2);
    }
#pragma unroll
    for (int cc = 0; cc < 4; cc++)
#pragma unroll
      for (int a = 0; a < 4; a++) wv[cc][a] = ws2[(c0 + cc) * 32 + oi * 4 + a];
#pragma unroll
    for (int cc = 0; cc < 4; cc++)
#pragma unroll
      for (int a = 0; a < 4; a++) {
        acc2[a][0] = fma2(wv[cc][a], xv[cc][0], acc2[a][0]);
        acc2[a][1] = fma2(wv[cc][a], xv[cc][1], acc2[a][1]);
      }
  }

#pragma unroll
  for (int a = 0; a < 4; a++) {
    int o = og * 32 + oi * 4 + a;
    float bb = bias[o];
    float* ob = out + (b * 128 + 64 + o) * HW + p0;
#pragma unroll
    for (int k = 0; k < 2; k++) {
      float lo, hi; unpack2(acc2[a][k], lo, hi);
      *(float2*)(ob + 64 * k + pi * 2) = make_float2(lo + bb, hi + bb);
    }
  }

  if (og == 0) {
    for (int i = t; i < 64 * 128; i += 256) {
      int oc = i >> 7, pp = i & 127;
      int idx = (b * 64 + oc) * HW + p0 + pp;
      float s = convp[idx] + convp[idx + 512 * HW] +
                convp[idx + 1024 * HW] + convp[idx + 1536 * HW];
      out[(b * 128 + oc) * HW + p0 + pp] = s + conv_b[oc];
    }
  }
}

// ---------------------------------------------------------------------------
extern "C" void kernel_launch(void* const* d_in, const int* in_sizes, int n_in,
                              void* d_out, int out_size) {
  (void)in_sizes; (void)n_in; (void)out_size;
  const float* x      = (const float*)d_in[0];
  const float* conv_w = (const float*)d_in[1];
  const float* conv_b = (const float*)d_in[2];
  const float* qkv_w  = (const float*)d_in[3];
  const float* qkv_b  = (const float*)d_in[4];
  const float* attn_w = (const float*)d_in[5];
  const float* attn_b = (const float*)d_in[6];
  const float* relw   = (const float*)d_in[7];
  const float* relh   = (const float*)d_in[8];
  float* out = (float*)d_out;

  float *qkv_s = nullptr, *convp = nullptr, *pacc = nullptr, *pssum = nullptr;
  cudaGetSymbolAddress((void**)&qkv_s, g_qkv);
  cudaGetSymbolAddress((void**)&convp, g_convp);
  cudaGetSymbolAddress((void**)&pacc, g_pacc);
  cudaGetSymbolAddress((void**)&pssum, g_pssum);

  const int PREP_SMEM = 49152;
  const int PROJ_SMEM = 4096 + 32768 + 16384;
  cudaFuncSetAttribute(prep_kernel, cudaFuncAttributeMaxDynamicSharedMemorySize, PREP_SMEM);
  cudaFuncSetAttribute(attn_kernel, cudaFuncAttributeMaxDynamicSharedMemorySize, AT4_SMEM);
  cudaFuncSetAttribute(proj_kernel, cudaFuncAttributeMaxDynamicSharedMemorySize, PROJ_SMEM);

  prep_kernel<<<896, 256, PREP_SMEM>>>(x, conv_w, qkv_w, qkv_b, convp, qkv_s);
  attn_kernel<<<dim3(64, 4, 4), 128, AT4_SMEM>>>(qkv_s, relw, relh, pacc, pssum);
  proj_kernel<<<dim3(8, 2, 8), 256, PROJ_SMEM>>>(pacc, pssum, convp, conv_b,
                                                 attn_w, attn_b, out);
}

// round 12
// speedup vs baseline: 1.1166x; 1.0633x over previous
#include <cuda_runtime.h>

#define HW 1024

// Scratch buffers
__device__ float g_qkv[8 * 192 * HW];        // [b][192][1024]; q pre-scaled by dkh^-0.5*log2e
__device__ float g_convp[4 * 8 * 64 * HW];   // [cs][b][64][1024] conv partial sums (no bias)
__device__ float g_pacc[4 * 8 * 64 * HW];    // [wq][b][64][1024] partial softmax-weighted V sums
__device__ float g_pssum[4 * 8 * 8 * HW];    // [wq][b][n][1024] partial exp sums

typedef unsigned long long u64;

__device__ __forceinline__ u64 fma2(u64 a, u64 b, u64 c) {
  u64 d; asm("fma.rn.f32x2 %0,%1,%2,%3;" : "=l"(d) : "l"(a), "l"(b), "l"(c)); return d;
}
__device__ __forceinline__ u64 add2(u64 a, u64 b) {
  u64 d; asm("add.rn.f32x2 %0,%1,%2;" : "=l"(d) : "l"(a), "l"(b)); return d;
}
__device__ __forceinline__ u64 pack2(float lo, float hi) {
  u64 d; asm("mov.b64 %0,{%1,%2};" : "=l"(d) : "f"(lo), "f"(hi)); return d;
}
__device__ __forceinline__ void unpack2(u64 v, float& lo, float& hi) {
  asm("mov.b64 {%0,%1},%2;" : "=f"(lo), "=f"(hi) : "l"(v));
}
__device__ __forceinline__ float ex2f(float x) {
  float y; asm("ex2.approx.ftz.f32 %0,%1;" : "=f"(y) : "f"(x)); return y;
}

// ---------------------------------------------------------------------------
// Fused prep (unchanged).
// blocks [0,512): conv3x3 c-split partials; blocks [512,896): qkv projection.
// ---------------------------------------------------------------------------
__global__ __launch_bounds__(256, 3) void prep_kernel(
    const float* __restrict__ x,
    const float* __restrict__ conv_w,
    const float* __restrict__ qkv_w, const float* __restrict__ qkv_b,
    float* __restrict__ convp, float* __restrict__ qkv_out) {
  extern __shared__ char smraw[];
  int blk = blockIdx.x;
  int t = threadIdx.x;

  if (blk < 512) {
    u64* wdup = (u64*)smraw;                 // [4 o][16 c][9] dup u64
    float* xs = (float*)(smraw + 4608);      // [8 cc][34][34] planar
    int cs = blk >> 7;
    int rem = blk & 127;
    int b = rem >> 4, og = rem & 15;
    int cbase = cs * 16;

    for (int i = t; i < 576; i += 256) {
      int o = i / 144, r2 = i - o * 144;
      float wv = conv_w[(og * 4 + o) * 576 + cbase * 9 + r2];
      wdup[i] = pack2(wv, wv);
    }
    for (int i = t; i < 9248; i += 256) xs[i] = 0.f;

    int xcol = t & 31, m0 = t >> 5;
    u64 acc[4][2];
#pragma unroll
    for (int o = 0; o < 4; o++) { acc[o][0] = 0ull; acc[o][1] = 0ull; }

    for (int chunk = 0; chunk < 2; chunk++) {
      __syncthreads();
#pragma unroll
      for (int cc = 0; cc < 8; cc++) {
        const float* xp = x + (b * 64 + cbase + chunk * 8 + cc) * HW;
#pragma unroll
        for (int rg = 0; rg < 4; rg++) {
          int row = rg * 8 + m0;
          xs[cc * 1156 + (row + 1) * 34 + xcol + 1] = xp[row * 32 + xcol];
        }
      }
      __syncthreads();

#pragma unroll
      for (int cc = 0; cc < 8; cc++) {
        const float* xc = xs + cc * 1156;
        int crel = chunk * 8 + cc;
        u64 pr[2][9];
#pragma unroll
        for (int pi = 0; pi < 2; pi++) {
          int m = m0 + pi * 8;
          const float* base = xc + (2 * m) * 34 + xcol;
#pragma unroll
          for (int kw = 0; kw < 3; kw++) {
            float s0 = base[kw], s1 = base[34 + kw];
            float s2 = base[68 + kw], s3 = base[102 + kw];
            pr[pi][0 + kw] = pack2(s0, s1);
            pr[pi][3 + kw] = pack2(s1, s2);
            pr[pi][6 + kw] = pack2(s2, s3);
          }
        }
        const u64* wc = wdup + crel * 9;
#pragma unroll
        for (int o = 0; o < 4; o++) {
          const u64* wo = wc + o * 144;
          u64 a0 = acc[o][0], a1 = acc[o][1];
#pragma unroll
          for (int k = 0; k < 9; k++) {
            u64 wk = wo[k];
            a0 = fma2(pr[0][k], wk, a0);
            a1 = fma2(pr[1][k], wk, a1);
          }
          acc[o][0] = a0; acc[o][1] = a1;
        }
      }
    }

    float* cpb = convp + (cs * 8 + b) * 64 * HW + og * 4 * HW;
#pragma unroll
    for (int o = 0; o < 4; o++) {
#pragma unroll
      for (int pi = 0; pi < 2; pi++) {
        int m = m0 + pi * 8;
        float lo, hi; unpack2(acc[o][pi], lo, hi);
        cpb[o * HW + (2 * m) * 32 + xcol] = lo;
        cpb[o * HW + (2 * m + 1) * 32 + xcol] = hi;
      }
    }
  } else {
    float* xs = (float*)smraw;               // [64][128] 32KB
    u64* ws2 = (u64*)(smraw + 32768);        // [64][32]  16KB
    int r = blk - 512;
    int b = r / 48;
    int rem = r - b * 48;
    int og = rem >> 3, pt = rem & 7;
    int p0 = pt * 128;

    for (int i = t; i < 64 * 128; i += 256) {
      int c = i >> 7, pp = i & 127;
      xs[i] = x[(b * 64 + c) * HW + p0 + pp];
    }
    for (int i = t; i < 64 * 32; i += 256) {
      int c = i >> 5, o = i & 31;
      float wv = qkv_w[(og * 32 + o) * 64 + c];
      ws2[i] = pack2(wv, wv);
    }
    __syncthreads();

    int oi = t >> 5, pi = t & 31;
    u64 acc2[4][2];
#pragma unroll
    for (int a = 0; a < 4; a++) { acc2[a][0] = 0ull; acc2[a][1] = 0ull; }

    for (int c0 = 0; c0 < 64; c0 += 4) {
      u64 xv[4][2], wv[4][4];
#pragma unroll
      for (int cc = 0; cc < 4; cc++) {
        xv[cc][0] = *(const u64*)(xs + (c0 + cc) * 128 + pi * 2);
        xv[cc][1] = *(const u64*)(xs + (c0 + cc) * 128 + 64 + pi * 2);
      }
#pragma unroll
      for (int cc = 0; cc < 4; cc++)
#pragma unroll
        for (int a = 0; a < 4; a++) wv[cc][a] = ws2[(c0 + cc) * 32 + oi * 4 + a];
#pragma unroll
      for (int cc = 0; cc < 4; cc++)
#pragma unroll
        for (int a = 0; a < 4; a++) {
          acc2[a][0] = fma2(wv[cc][a], xv[cc][0], acc2[a][0]);
          acc2[a][1] = fma2(wv[cc][a], xv[cc][1], acc2[a][1]);
        }
    }

#pragma unroll
    for (int a = 0; a < 4; a++) {
      int o = og * 32 + oi * 4 + a;
      float bb = qkv_b[o];
      float sc = (o < 64) ? (0.35355339059327373f * 1.4426950408889634f) : 1.f;
      float* ob = qkv_out + (b * 192 + o) * HW + p0;
#pragma unroll
      for (int k = 0; k < 2; k++) {
        float lo, hi; unpack2(acc2[a][k], lo, hi);
        *(float2*)(ob + 64 * k + pi * 2) = make_float2(sc * (lo + bb), sc * (hi + bb));
      }
    }
  }
}

// ---------------------------------------------------------------------------
// Attention v5: j-pair f32x2 dataflow with (a) per-warp h2 phase STAGGER so
// co-resident warps overlap fma/MUFU/alu pipes, (b) 8 merged logit chains +
// 16 batched ex2 per h2, (c) rw table in registers (no smem rwt).
// grid (64 bn, 4 rowg, 4 wq), block 128; thread owns rows (i0, i0+1).
// smem 24.4KB -> 4 blocks/SM; reg cap 124 via __launch_bounds__(128, 4).
// ---------------------------------------------------------------------------
#define AT5_K    0                     // [8 d][256 jl] f32 = 8192
#define AT5_V    8192                  // 8192
#define AT5_RELW 16384                 // 504 u64 dup = 4032
#define AT5_RELH 20416                 // 4032
#define AT5_SMEM 24448

__global__ __launch_bounds__(128, 4) void attn_kernel(
    const float* __restrict__ qkv,
    const float* __restrict__ relw, const float* __restrict__ relh,
    float* __restrict__ pacc, float* __restrict__ pssum) {
  extern __shared__ char sm[];
  float* kpl = (float*)(sm + AT5_K);
  float* vpl = (float*)(sm + AT5_V);
  u64* relwd = (u64*)(sm + AT5_RELW);
  u64* relhd = (u64*)(sm + AT5_RELH);
  int t = threadIdx.x;
  int bn = blockIdx.x;
  int b = bn >> 3, n = bn & 7;
  int rowg = blockIdx.y;   // 0..3
  int wq = blockIdx.z;     // 0..3

  const float* qb = qkv + (b * 192 + n * 8) * HW;
  const float* kb = qkv + (b * 192 + 64 + n * 8) * HW;
  const float* vb = qkv + (b * 192 + 128 + n * 8) * HW;

  // stage K,V planar: jl = h2*8 + w2l <-> j = h2*32 + wq*8 + w2l
  for (int e = t; e < 2048; e += 128) {
    int d = e >> 8, jl = e & 255;
    int j = (jl >> 3) * 32 + wq * 8 + (jl & 7);
    kpl[e] = kb[d * HW + j];
    vpl[e] = vb[d * HW + j];
  }
  for (int e = t; e < 504; e += 128) {
    float a = relw[e]; relwd[e] = pack2(a, a);
    float c = relh[e]; relhd[e] = pack2(c, c);
  }
  __syncthreads();

  int i0 = rowg * 256 + 2 * t;       // rows i0, i0+1 (same h1; w1 <= 30)
  int h1 = i0 >> 5, w1 = i0 & 31;
  int wid = t >> 5;                  // warp id 0..3 -> h2 phase offset

  u64 q2[2][8];
#pragma unroll
  for (int d = 0; d < 8; d++) {
    float2 qv = *(const float2*)(qb + d * HW + i0);
    q2[0][d] = pack2(qv.x, qv.x);
    q2[1][d] = pack2(qv.y, qv.y);
  }

  // rw table in registers: myrw[r*4+p] = (rw[r][w2=wq*8+2p], rw[r][w2+1])
  u64 myrw[8];
#pragma unroll
  for (int r = 0; r < 2; r++) {
#pragma unroll
    for (int p = 0; p < 4; p++) {
      int m0 = wq * 8 + 2 * p - (w1 + r) + 31;
      u64 z0 = 0ull, z1 = 0ull;
#pragma unroll
      for (int d = 0; d < 8; d++) {
        z0 = fma2(q2[r][d], relwd[m0 * 8 + d], z0);
        z1 = fma2(q2[r][d], relwd[(m0 + 1) * 8 + d], z1);
      }
      float alo, ahi, blo, bhi;
      unpack2(z0, alo, ahi); unpack2(z1, blo, bhi);
      myrw[r * 4 + p] = pack2(alo, blo);
    }
  }

  u64 acc2[2][8];
  u64 ssum2[2] = {0ull, 0ull};
#pragma unroll
  for (int d = 0; d < 8; d++) { acc2[0][d] = 0ull; acc2[1][d] = 0ull; }

#pragma unroll 1
  for (int hh = 0; hh < 32; hh++) {
    int h2 = (hh + wid * 8) & 31;     // per-warp phase stagger
    const u64* rhp = relhd + (h2 - h1 + 31) * 8;
    u64 rh0 = 0ull, rh1 = 0ull;
#pragma unroll
    for (int d = 0; d < 8; d++) {
      u64 rv = rhp[d];
      rh0 = fma2(q2[0][d], rv, rh0);
      rh1 = fma2(q2[1][d], rv, rh1);
    }

    // 8 independent logit chains: s[r*4+p] covers j-pair (h2*8+2p, +1)
    u64 s[8];
#pragma unroll
    for (int p = 0; p < 4; p++) {
      s[p] = add2(myrw[p], rh0);
      s[4 + p] = add2(myrw[4 + p], rh1);
    }
    int base = h2 * 8;
#pragma unroll
    for (int d = 0; d < 8; d++) {
      ulonglong2 kkA = *(const ulonglong2*)(kpl + d * 256 + base);
      ulonglong2 kkB = *(const ulonglong2*)(kpl + d * 256 + base + 4);
      u64 qa = q2[0][d], qb2 = q2[1][d];
      s[0] = fma2(qa, kkA.x, s[0]); s[1] = fma2(qa, kkA.y, s[1]);
      s[2] = fma2(qa, kkB.x, s[2]); s[3] = fma2(qa, kkB.y, s[3]);
      s[4] = fma2(qb2, kkA.x, s[4]); s[5] = fma2(qb2, kkA.y, s[5]);
      s[6] = fma2(qb2, kkB.x, s[6]); s[7] = fma2(qb2, kkB.y, s[7]);
    }

    // 16 batched ex2
    u64 pexp[8];
#pragma unroll
    for (int k = 0; k < 8; k++) {
      float lo, hi; unpack2(s[k], lo, hi);
      pexp[k] = pack2(ex2f(lo), ex2f(hi));
    }
    ssum2[0] = add2(ssum2[0], add2(add2(pexp[0], pexp[1]), add2(pexp[2], pexp[3])));
    ssum2[1] = add2(ssum2[1], add2(add2(pexp[4], pexp[5]), add2(pexp[6], pexp[7])));

    // AV
#pragma unroll
    for (int d = 0; d < 8; d++) {
      ulonglong2 vvA = *(const ulonglong2*)(vpl + d * 256 + base);
      ulonglong2 vvB = *(const ulonglong2*)(vpl + d * 256 + base + 4);
      u64 a0 = acc2[0][d], a1 = acc2[1][d];
      a0 = fma2(pexp[0], vvA.x, a0); a0 = fma2(pexp[1], vvA.y, a0);
      a0 = fma2(pexp[2], vvB.x, a0); a0 = fma2(pexp[3], vvB.y, a0);
      a1 = fma2(pexp[4], vvA.x, a1); a1 = fma2(pexp[5], vvA.y, a1);
      a1 = fma2(pexp[6], vvB.x, a1); a1 = fma2(pexp[7], vvB.y, a1);
      acc2[0][d] = a0; acc2[1][d] = a1;
    }
  }

  float s0lo, s0hi, s1lo, s1hi;
  unpack2(ssum2[0], s0lo, s0hi);
  unpack2(ssum2[1], s1lo, s1hi);
  *(float2*)(pssum + ((wq * 8 + b) * 8 + n) * HW + i0) =
      make_float2(s0lo + s0hi, s1lo + s1hi);
  float* ab = pacc + ((wq * 8 + b) * 64 + n * 8) * HW + i0;
#pragma unroll
  for (int d = 0; d < 8; d++) {
    float a0, a1, b0, b1;
    unpack2(acc2[0][d], a0, a1);
    unpack2(acc2[1][d], b0, b1);
    *(float2*)(ab + d * HW) = make_float2(a0 + a1, b0 + b1);
  }
}

// ---------------------------------------------------------------------------
// Output projection (unchanged): merges 4 attn partials + softmax division +
// GEMM (ch 64..127); og==0 blocks merge the 4 conv partials (ch 0..63).
// ---------------------------------------------------------------------------
__global__ __launch_bounds__(256) void proj_kernel(
    const float* __restrict__ pacc, const float* __restrict__ pssum,
    const float* __restrict__ convp, const float* __restrict__ conv_b,
    const float* __restrict__ w, const float* __restrict__ bias,
    float* __restrict__ out) {
  extern __shared__ char smraw[];
  float* invs = (float*)smraw;                     // [8][128] 4KB
  float* xs = (float*)(smraw + 4096);              // [64][128] 32KB
  u64* ws2 = (u64*)(smraw + 4096 + 32768);         // [64][32] 16KB
  int b = blockIdx.x, og = blockIdx.y, pt = blockIdx.z;
  int t = threadIdx.x;
  int p0 = pt * 128;

  for (int i = t; i < 1024; i += 256) {
    int n = i >> 7, pp = i & 127;
    int idx = (b * 8 + n) * HW + p0 + pp;
    float s = pssum[idx] + pssum[idx + 64 * HW] +
              pssum[idx + 128 * HW] + pssum[idx + 192 * HW];
    invs[i] = 1.f / s;
  }
  for (int i = t; i < 64 * 32; i += 256) {
    int c = i >> 5, o = i & 31;
    float wv = w[(og * 32 + o) * 64 + c];
    ws2[i] = pack2(wv, wv);
  }
  __syncthreads();
  for (int i = t; i < 64 * 128; i += 256) {
    int c = i >> 7, pp = i & 127;
    int idx = (b * 64 + c) * HW + p0 + pp;
    float s = pacc[idx] + pacc[idx + 512 * HW] +
              pacc[idx + 1024 * HW] + pacc[idx + 1536 * HW];
    xs[i] = s * invs[(c >> 3) * 128 + pp];
  }
  __syncthreads();

  int oi = t >> 5, pi = t & 31;
  u64 acc2[4][2];
#pragma unroll
  for (int a = 0; a < 4; a++) { acc2[a][0] = 0ull; acc2[a][1] = 0ull; }

  for (int c0 = 0; c0 < 64; c0 += 4) {
    u64 xv[4][2], wv[4][4];
#pragma unroll
    for (int cc = 0; cc < 4; cc++) {
      xv[cc][0] = *(const u64*)(xs + (c0 + cc) * 128 + pi * 2);
      xv[cc][1] = *(const u64*)(xs + (c0 + cc) * 128 + 64 + pi * 2);
    }
#pragma unroll
    for (int cc = 0; cc < 4; cc++)
#pragma unroll
      for (int a = 0; a < 4; a++) wv[cc][a] = ws2[(c0 + cc) * 32 + oi * 4 + a];
#pragma unroll
    for (int cc = 0; cc < 4; cc++)
#pragma unroll
      for (int a = 0; a < 4; a++) {
        acc2[a][0] = fma2(wv[cc][a], xv[cc][0], acc2[a][0]);
        acc2[a][1] = fma2(wv[cc][a], xv[cc][1], acc2[a][1]);
      }
  }

#pragma unroll
  for (int a = 0; a < 4; a++) {
    int o = og * 32 + oi * 4 + a;
    float bb = bias[o];
    float* ob = out + (b * 128 + 64 + o) * HW + p0;
#pragma unroll
    for (int k = 0; k < 2; k++) {
      float lo, hi; unpack2(acc2[a][k], lo, hi);
      *(float2*)(ob + 64 * k + pi * 2) = make_float2(lo + bb, hi + bb);
    }
  }

  if (og == 0) {
    for (int i = t; i < 64 * 128; i += 256) {
      int oc = i >> 7, pp = i & 127;
      int idx = (b * 64 + oc) * HW + p0 + pp;
      float s = convp[idx] + convp[idx + 512 * HW] +
                convp[idx + 1024 * HW] + convp[idx + 1536 * HW];
      out[(b * 128 + oc) * HW + p0 + pp] = s + conv_b[oc];
    }
  }
}

// ---------------------------------------------------------------------------
extern "C" void kernel_launch(void* const* d_in, const int* in_sizes, int n_in,
                              void* d_out, int out_size) {
  (void)in_sizes; (void)n_in; (void)out_size;
  const float* x      = (const float*)d_in[0];
  const float* conv_w = (const float*)d_in[1];
  const float* conv_b = (const float*)d_in[2];
  const float* qkv_w  = (const float*)d_in[3];
  const float* qkv_b  = (const float*)d_in[4];
  const float* attn_w = (const float*)d_in[5];
  const float* attn_b = (const float*)d_in[6];
  const float* relw   = (const float*)d_in[7];
  const float* relh   = (const float*)d_in[8];
  float* out = (float*)d_out;

  float *qkv_s = nullptr, *convp = nullptr, *pacc = nullptr, *pssum = nullptr;
  cudaGetSymbolAddress((void**)&qkv_s, g_qkv);
  cudaGetSymbolAddress((void**)&convp, g_convp);
  cudaGetSymbolAddress((void**)&pacc, g_pacc);
  cudaGetSymbolAddress((void**)&pssum, g_pssum);

  const int PREP_SMEM = 49152;
  const int PROJ_SMEM = 4096 + 32768 + 16384;
  cudaFuncSetAttribute(prep_kernel, cudaFuncAttributeMaxDynamicSharedMemorySize, PREP_SMEM);
  cudaFuncSetAttribute(attn_kernel, cudaFuncAttributeMaxDynamicSharedMemorySize, AT5_SMEM);
  cudaFuncSetAttribute(proj_kernel, cudaFuncAttributeMaxDynamicSharedMemorySize, PROJ_SMEM);

  prep_kernel<<<896, 256, PREP_SMEM>>>(x, conv_w, qkv_w, qkv_b, convp, qkv_s);
  attn_kernel<<<dim3(64, 4, 4), 128, AT5_SMEM>>>(qkv_s, relw, relh, pacc, pssum);
  proj_kernel<<<dim3(8, 2, 8), 256, PROJ_SMEM>>>(pacc, pssum, convp, conv_b,
                                                 attn_w, attn_b, out);
}